// round 11
// baseline (speedup 1.0000x reference)
#include <cuda_runtime.h>
#include <cstdint>

// B=2, C=128, IC=64, W=H=32, Z=128, nz=64. 2048 tiles of x[C=128][Z=128].
// Warp-level tf32 mma.sync m16n8k8 (base sm_103 target; tcgen05 is 'a'-gated).
//   GEMM1 D1[o=128][z=128] = Wgp[o][Ci] @ x[Ci][z]   (g rows 0..63, phi 64..127)
//   epi1: pool z-pairs (in-register); g -> gp[j][c]/64, phi -> bb partials; a[z]=vt.x
//   GEMM2 D2[z][c=64] = f @ gp, f = relu(a+bb);  y in place
//   GEMM3 D3[z][Co=128] = y @ Ww^T ; out = D3*alpha + beta + x
// R11: register diet for 3 CTAs/SM — GEMM1 as two 32-accum z-passes (pooled regs
// held across passes), GEMM3 as two 32-accum row-passes; launch_bounds(256,3).

#define N_TILES 2048
#define THREADS 256

__device__ __forceinline__ float to_tf32(float v) {
    uint32_t u; asm("cvt.rna.tf32.f32 %0, %1;" : "=r"(u) : "f"(v));
    return __uint_as_float(u);
}
__device__ __forceinline__ void mma8(float* d, uint32_t a0, uint32_t a1, uint32_t a2,
                                     uint32_t a3, uint32_t b0, uint32_t b1) {
    asm volatile("mma.sync.aligned.m16n8k8.row.col.f32.tf32.tf32.f32 "
                 "{%0,%1,%2,%3}, {%4,%5,%6,%7}, {%8,%9}, {%0,%1,%2,%3};"
                 : "+f"(d[0]), "+f"(d[1]), "+f"(d[2]), "+f"(d[3])
                 : "r"(a0), "r"(a1), "r"(a2), "r"(a3), "r"(b0), "r"(b1));
}

// ---- precomputed globals ----
__device__ float d_vt[128];      // cat_w[:64]^T @ theta_w (theta conv collapsed)
__device__ float d_ct;
__device__ float d_alpha[128];
__device__ float d_beta[128];
__device__ float d_A1f[16384];   // Wgp frags: [strip8][ks16][lane32][r4] (tf32)
__device__ float d_WwB[8192];    // Ww  frags: [ks8][nt16][lane32][r2]    (tf32)

__global__ void setup_kernel(const float* __restrict__ theta_w,
                             const float* __restrict__ theta_b,
                             const float* __restrict__ cat_w,
                             const float* __restrict__ W_b,
                             const float* __restrict__ bn_g,
                             const float* __restrict__ bn_b,
                             const float* __restrict__ bn_m,
                             const float* __restrict__ bn_v,
                             const float* __restrict__ g_w,
                             const float* __restrict__ phi_w,
                             const float* __restrict__ W_w)
{
    int tid = threadIdx.x;  // 256
    if (tid < 128) {
        float s = 0.f;
        for (int ic = 0; ic < 64; ic++) s += cat_w[ic] * theta_w[ic * 128 + tid];
        d_vt[tid] = s;
        float a = bn_g[tid] * rsqrtf(bn_v[tid] + 1e-5f);
        d_alpha[tid] = a;
        d_beta[tid]  = (W_b[tid] - bn_m[tid]) * a + bn_b[tid];
    }
    if (tid == 0) {
        float s = 0.f;
        for (int ic = 0; ic < 64; ic++) s += cat_w[ic] * theta_b[ic];
        d_ct = s;
    }
    // A frags GEMM1: a0:(row,col) a1:(row+8,col) a2:(row,col+4) a3:(row+8,col+4)
    for (int idx = tid; idx < 16384; idx += 256) {
        int r = idx & 3, lane = (idx >> 2) & 31, ks = (idx >> 7) & 15, s = idx >> 11;
        int o  = s * 16 + (lane >> 2) + (r & 1) * 8;
        int Ci = ks * 8 + (lane & 3) + ((r >> 1) & 1) * 4;
        float v = (o < 64) ? g_w[o * 128 + Ci] : phi_w[(o - 64) * 128 + Ci];
        d_A1f[idx] = to_tf32(v);
    }
    // B frags GEMM3: b0:(k,n) b1:(k+4,n); k=c, n=Co
    for (int idx = tid; idx < 8192; idx += 256) {
        int r = idx & 1, lane = (idx >> 1) & 31, nt = (idx >> 6) & 15, ks = idx >> 10;
        int c  = ks * 8 + (lane & 3) + r * 4;
        int Co = nt * 8 + (lane >> 2);
        d_WwB[idx] = to_tf32(W_w[Co * 64 + c]);
    }
}

// ---- smem layout (floats). x region overlaid by f/gp after GEMM1. ----
#define OFF_X    0        // x [Ci=128][136]
#define OFF_F    0        // f/y [z=128][68]  -- overlay
#define OFF_GP   8704     // gp [j=64][72]    -- overlay (fits inside x region)
#define OFF_AS   17408    // a partials [2][128]
#define OFF_BBW  17664    // bb partials [2][64]
#define OFF_GB   17792
#define OFF_PB   17856
#define OFF_WP   17920
#define OFF_AL   17984
#define OFF_BE   18112
#define OFF_VT   18240
#define SMEM_FLOATS 18368
#define SMEM_BYTES (SMEM_FLOATS * 4)   // 73472 -> 3 CTAs/SM (220416 <= 228KB)

__global__ void __launch_bounds__(THREADS, 3)
nonlocal_kernel(const float* __restrict__ x,
                const float* __restrict__ g_b,
                const float* __restrict__ phi_b,
                const float* __restrict__ cat_w,
                float* __restrict__ out)
{
    extern __shared__ float sm[];
    const int tid  = threadIdx.x;
    const int lane = tid & 31;
    const int wid  = tid >> 5;     // 0..7
    const int q    = lane & 3;
    const int l4   = lane >> 2;

    const int n  = blockIdx.x;
    const int b  = n >> 10;
    const int wh = n & 1023;
    const size_t gbase = (size_t)b * 16777216 + (size_t)wh * 128;  // + Ci*131072 + z
    const float* xg = x + gbase;

    // ---- stage A: load x tile + small vectors ----
    {
        const float4* xg4 = (const float4*)xg;
        #pragma unroll
        for (int it = 0; it < 16; it++) {
            int idx = it * 256 + tid;            // 4096 float4
            int Ci = idx >> 5, z4 = idx & 31;
            *(float4*)(sm + OFF_X + Ci * 136 + z4 * 4) = xg4[(size_t)Ci * 32768 + z4];
        }
    }
    if (tid < 128) { sm[OFF_VT + tid] = d_vt[tid]; sm[OFF_AL + tid] = d_alpha[tid]; sm[OFF_BE + tid] = d_beta[tid]; }
    if (tid < 64)  { sm[OFF_GB + tid] = g_b[tid]; sm[OFF_PB + tid] = phi_b[tid]; sm[OFF_WP + tid] = cat_w[64 + tid]; }
    __syncthreads();

    // ---- a[z] partials over all 256 threads (half the Ci range each) ----
    {
        const int z = tid & 127, h = tid >> 7;
        float s = h ? 0.f : d_ct;
        const int c0 = h * 64;
        #pragma unroll 8
        for (int Ci = c0; Ci < c0 + 64; Ci++)
            s = fmaf(sm[OFF_VT + Ci], sm[OFF_X + Ci * 136 + z], s);
        sm[OFF_AS + h * 128 + z] = s;
    }

    // ---- GEMM1: two z-passes; warp grid 4 o-strips(32) x 2 z-quarters(32) ----
    const int oz = wid & 3;        // o-strip of 32 (2 frag strips)
    const int zq = wid >> 2;       // z quarter within pass

    float pool[2][2][4][2];        // [pass][mt][nt][row01]  (pooled z-pairs)
    {
        const float4* gA0 = ((const float4*)d_A1f) + (oz * 2) * 512;
        const float4* gA1 = gA0 + 512;
        #pragma unroll 1
        for (int pass = 0; pass < 2; pass++) {
            const int zbase = 64 * pass + 32 * zq;
            float d1[2][4][4];
            #pragma unroll
            for (int mt = 0; mt < 2; mt++)
                #pragma unroll
                for (int nt = 0; nt < 4; nt++)
                    #pragma unroll
                    for (int r = 0; r < 4; r++) d1[mt][nt][r] = 0.f;

            float4 af0 = gA0[lane], af1 = gA1[lane];
            #pragma unroll 1
            for (int ks = 0; ks < 16; ks++) {
                float4 c0 = af0, c1 = af1;
                if (ks < 15) { af0 = gA0[(ks + 1) * 32 + lane]; af1 = gA1[(ks + 1) * 32 + lane]; }
                uint32_t a00 = __float_as_uint(c0.x), a01 = __float_as_uint(c0.y);
                uint32_t a02 = __float_as_uint(c0.z), a03 = __float_as_uint(c0.w);
                uint32_t a10 = __float_as_uint(c1.x), a11 = __float_as_uint(c1.y);
                uint32_t a12 = __float_as_uint(c1.z), a13 = __float_as_uint(c1.w);
                const float* xr0 = sm + OFF_X + (8 * ks + q) * 136 + zbase + l4;
                const float* xr1 = xr0 + 4 * 136;
                #pragma unroll
                for (int nt = 0; nt < 4; nt++) {
                    uint32_t b0 = __float_as_uint(xr0[8 * nt]);
                    uint32_t b1 = __float_as_uint(xr1[8 * nt]);
                    mma8(d1[0][nt], a00, a01, a02, a03, b0, b1);
                    mma8(d1[1][nt], a10, a11, a12, a13, b0, b1);
                }
            }
            #pragma unroll
            for (int mt = 0; mt < 2; mt++)
                #pragma unroll
                for (int nt = 0; nt < 4; nt++) {
                    pool[pass][mt][nt][0] = fmaxf(d1[mt][nt][0], d1[mt][nt][1]);
                    pool[pass][mt][nt][1] = fmaxf(d1[mt][nt][2], d1[mt][nt][3]);
                }
        }
    }
    __syncthreads();   // all x reads done -> overlay (gp/f) writable

    // ---- epi1: gp (g warps) / bb partials (phi warps) from pooled regs ----
    if (oz < 2) {
        #pragma unroll
        for (int pass = 0; pass < 2; pass++)
            #pragma unroll
            for (int mt = 0; mt < 2; mt++) {
                const int o0 = oz * 32 + 16 * mt + l4, o1 = o0 + 8;
                const float gb0 = sm[OFF_GB + o0], gb1 = sm[OFF_GB + o1];
                #pragma unroll
                for (int nt = 0; nt < 4; nt++) {
                    int j = 32 * pass + 16 * zq + 4 * nt + q;
                    sm[OFF_GP + j * 72 + o0] = (pool[pass][mt][nt][0] + gb0) * 0.015625f;
                    sm[OFF_GP + j * 72 + o1] = (pool[pass][mt][nt][1] + gb1) * 0.015625f;
                }
            }
    } else {
        #pragma unroll
        for (int pass = 0; pass < 2; pass++)
            #pragma unroll
            for (int nt = 0; nt < 4; nt++) {
                float v = 0.f;
                #pragma unroll
                for (int mt = 0; mt < 2; mt++) {
                    const int p0 = (oz - 2) * 32 + 16 * mt + l4, p1 = p0 + 8;
                    v += sm[OFF_WP + p0] * (pool[pass][mt][nt][0] + sm[OFF_PB + p0])
                       + sm[OFF_WP + p1] * (pool[pass][mt][nt][1] + sm[OFF_PB + p1]);
                }
                v += __shfl_xor_sync(0xFFFFFFFFu, v, 16);
                v += __shfl_xor_sync(0xFFFFFFFFu, v, 8);
                v += __shfl_xor_sync(0xFFFFFFFFu, v, 4);
                if (l4 == 0)
                    sm[OFF_BBW + (oz - 2) * 64 + 32 * pass + 16 * zq + 4 * nt + q] = v;
            }
    }
    __syncthreads();

    {   // f[z][j] = relu(a[z] + bbw0[j] + bbw1[j])
        const int z = tid >> 1, half = tid & 1;
        const float az = sm[OFF_AS + z] + sm[OFF_AS + 128 + z];
        #pragma unroll
        for (int jj = 0; jj < 8; jj++) {
            int j = half * 32 + 4 * jj;
            float4 v;
            v.x = fmaxf(az + sm[OFF_BBW + j + 0] + sm[OFF_BBW + 64 + j + 0], 0.f);
            v.y = fmaxf(az + sm[OFF_BBW + j + 1] + sm[OFF_BBW + 64 + j + 1], 0.f);
            v.z = fmaxf(az + sm[OFF_BBW + j + 2] + sm[OFF_BBW + 64 + j + 2], 0.f);
            v.w = fmaxf(az + sm[OFF_BBW + j + 3] + sm[OFF_BBW + 64 + j + 3], 0.f);
            *(float4*)(sm + OFF_F + z * 68 + j) = v;
        }
    }
    __syncthreads();

    // ---- GEMM2: D2[z][c] = f @ gp, warp = z-strip 16 (wid) ----
    {
        float d2[8][4];
        #pragma unroll
        for (int nt = 0; nt < 8; nt++)
            #pragma unroll
            for (int r = 0; r < 4; r++) d2[nt][r] = 0.f;

        #pragma unroll 1
        for (int ks = 0; ks < 8; ks++) {
            const float* fr = sm + OFF_F + (16 * wid + l4) * 68 + 8 * ks + q;
            uint32_t a0 = __float_as_uint(fr[0]);
            uint32_t a1 = __float_as_uint(fr[8 * 68]);
            uint32_t a2 = __float_as_uint(fr[4]);
            uint32_t a3 = __float_as_uint(fr[8 * 68 + 4]);
            const float* gr0 = sm + OFF_GP + (8 * ks + q) * 72 + l4;
            const float* gr1 = gr0 + 4 * 72;
            #pragma unroll
            for (int nt = 0; nt < 8; nt++) {
                uint32_t b0 = __float_as_uint(gr0[8 * nt]);
                uint32_t b1 = __float_as_uint(gr1[8 * nt]);
                mma8(d2[nt], a0, a1, a2, a3, b0, b1);
            }
        }
        // epi2: y overwrites own f strip
        #pragma unroll
        for (int nt = 0; nt < 8; nt++) {
            int c = 8 * nt + 2 * q;
            *(float2*)(sm + OFF_F + (16 * wid + l4) * 68 + c)     = make_float2(d2[nt][0], d2[nt][1]);
            *(float2*)(sm + OFF_F + (16 * wid + l4 + 8) * 68 + c) = make_float2(d2[nt][2], d2[nt][3]);
        }
    }
    __syncthreads();   // y read cross-warp in GEMM3

    // ---- GEMM3: warp grid 4 z-strips(32) x 2 Co-halves(64); two 32-accum passes ----
    {
        const int zq3 = wid >> 1, ch = wid & 1;
        const int zb3 = zq3 * 32, cob = ch * 64;
        const float2* gB = (const float2*)d_WwB;

        #pragma unroll 1
        for (int mt = 0; mt < 2; mt++) {
            float d3[8][4];
            #pragma unroll
            for (int nt = 0; nt < 8; nt++)
                #pragma unroll
                for (int r = 0; r < 4; r++) d3[nt][r] = 0.f;

            #pragma unroll 1
            for (int ks = 0; ks < 8; ks++) {
                const float* yr = sm + OFF_F + (zb3 + 16 * mt + l4) * 68 + 8 * ks + q;
                uint32_t a0 = __float_as_uint(yr[0]);
                uint32_t a1 = __float_as_uint(yr[8 * 68]);
                uint32_t a2 = __float_as_uint(yr[4]);
                uint32_t a3 = __float_as_uint(yr[8 * 68 + 4]);
                #pragma unroll
                for (int nt = 0; nt < 8; nt++) {
                    float2 bw = gB[(ks * 16 + ch * 8 + nt) * 32 + lane];
                    mma8(d3[nt], a0, a1, a2, a3,
                         __float_as_uint(bw.x), __float_as_uint(bw.y));
                }
            }

            const int z0 = zb3 + 16 * mt + l4, z1 = z0 + 8;
            #pragma unroll
            for (int nt = 0; nt < 8; nt++) {
                int Co0 = cob + 8 * nt + 2 * q, Co1 = Co0 + 1;
                float al0 = sm[OFF_AL + Co0], be0 = sm[OFF_BE + Co0];
                float al1 = sm[OFF_AL + Co1], be1 = sm[OFF_BE + Co1];
                size_t p00 = gbase + (size_t)Co0 * 131072 + z0;
                size_t p10 = gbase + (size_t)Co1 * 131072 + z0;
                size_t p01 = gbase + (size_t)Co0 * 131072 + z1;
                size_t p11 = gbase + (size_t)Co1 * 131072 + z1;
                out[p00] = fmaf(d3[nt][0], al0, be0) + __ldg(x + p00);
                out[p10] = fmaf(d3[nt][1], al1, be1) + __ldg(x + p10);
                out[p01] = fmaf(d3[nt][2], al0, be0) + __ldg(x + p01);
                out[p11] = fmaf(d3[nt][3], al1, be1) + __ldg(x + p11);
            }
        }
    }
}

extern "C" void kernel_launch(void* const* d_in, const int* in_sizes, int n_in,
                              void* d_out, int out_size)
{
    const float* x       = (const float*)d_in[0];
    const float* g_w     = (const float*)d_in[1];
    const float* g_b     = (const float*)d_in[2];
    const float* theta_w = (const float*)d_in[3];
    const float* theta_b = (const float*)d_in[4];
    const float* phi_w   = (const float*)d_in[5];
    const float* phi_b   = (const float*)d_in[6];
    const float* cat_w   = (const float*)d_in[7];
    const float* W_w     = (const float*)d_in[8];
    const float* W_b     = (const float*)d_in[9];
    const float* bn_g    = (const float*)d_in[10];
    const float* bn_b    = (const float*)d_in[11];
    const float* bn_m    = (const float*)d_in[12];
    const float* bn_v    = (const float*)d_in[13];

    cudaFuncSetAttribute(nonlocal_kernel,
                         cudaFuncAttributeMaxDynamicSharedMemorySize, SMEM_BYTES);

    setup_kernel<<<1, 256>>>(theta_w, theta_b, cat_w, W_b,
                             bn_g, bn_b, bn_m, bn_v, g_w, phi_w, W_w);
    nonlocal_kernel<<<N_TILES, THREADS, SMEM_BYTES>>>(x, g_b, phi_b, cat_w,
                                                      (float*)d_out);
}

// round 13
// speedup vs baseline: 1.6076x; 1.6076x over previous
#include <cuda_runtime.h>
#include <cuda_bf16.h>
#include <cstdint>

// B=2, C=128, IC=64, W=H=32, Z=128, nz=64. 2048 tiles of x[C=128][Z=128].
// R12: all GEMMs via mma.sync m16n8k16 bf16 (base sm_103 target; tcgen05 'a'-gated).
//   GEMM1 D1[o=128][z=128] = Wgp[o][Ci] @ x[Ci][z]   (g rows 0..63, phi 64..127)
//   epi1: pool z-pairs in-register; g -> gp[c][j]/64 bf16, phi -> bb partials; a[z]
//   GEMM2 D2[z][c=64] = f @ gp (f bf16), y in place (bf16)
//   GEMM3 D3[z][Co=128] = y @ Ww^T ; out = D3*alpha + beta + x (fp32 accum/epi)
// x transposed+converted at load: 4 coalesced LDG.32/lane -> bf16x2 pack -> STS.64.

#define N_TILES 2048
#define THREADS 256

__device__ __forceinline__ uint32_t pkbf(float lo, float hi) {
    uint32_t r;
    asm("cvt.rn.bf16x2.f32 %0, %1, %2;" : "=r"(r) : "f"(hi), "f"(lo));
    return r;
}
__device__ __forceinline__ float bf_lo(uint32_t u) { return __uint_as_float(u << 16); }
__device__ __forceinline__ float bf_hi(uint32_t u) { return __uint_as_float(u & 0xffff0000u); }

__device__ __forceinline__ void mma16(float* d, uint32_t a0, uint32_t a1, uint32_t a2,
                                      uint32_t a3, uint32_t b0, uint32_t b1) {
    asm volatile("mma.sync.aligned.m16n8k16.row.col.f32.bf16.bf16.f32 "
                 "{%0,%1,%2,%3}, {%4,%5,%6,%7}, {%8,%9}, {%0,%1,%2,%3};"
                 : "+f"(d[0]), "+f"(d[1]), "+f"(d[2]), "+f"(d[3])
                 : "r"(a0), "r"(a1), "r"(a2), "r"(a3), "r"(b0), "r"(b1));
}

// ---- precomputed globals ----
__device__ float d_vt[128];      // cat_w[:64]^T @ theta_w (theta conv collapsed)
__device__ float d_ct;
__device__ float d_alpha[128];
__device__ float d_beta[128];
__device__ __align__(16) uint32_t d_A1f[8192];  // Wgp bf16 frags [strip8][ks8][lane32][r4]
__device__ __align__(8)  uint32_t d_WwB[4096];  // Ww  bf16 frags [ks4][nt16][lane32][r2]

__global__ void setup_kernel(const float* __restrict__ theta_w,
                             const float* __restrict__ theta_b,
                             const float* __restrict__ cat_w,
                             const float* __restrict__ W_b,
                             const float* __restrict__ bn_g,
                             const float* __restrict__ bn_b,
                             const float* __restrict__ bn_m,
                             const float* __restrict__ bn_v,
                             const float* __restrict__ g_w,
                             const float* __restrict__ phi_w,
                             const float* __restrict__ W_w)
{
    int tid = threadIdx.x;  // 256
    if (tid < 128) {
        float s = 0.f;
        for (int ic = 0; ic < 64; ic++) s += cat_w[ic] * theta_w[ic * 128 + tid];
        d_vt[tid] = s;
        float a = bn_g[tid] * rsqrtf(bn_v[tid] + 1e-5f);
        d_alpha[tid] = a;
        d_beta[tid]  = (W_b[tid] - bn_m[tid]) * a + bn_b[tid];
    }
    if (tid == 0) {
        float s = 0.f;
        for (int ic = 0; ic < 64; ic++) s += cat_w[ic] * theta_b[ic];
        d_ct = s;
    }
    // A frags GEMM1 (m16n8k16, A row-major 16x16):
    // a0:(row,2q|2q+1) a1:(row+8,..) a2:(row,2q+8|+9) a3:(row+8,2q+8|+9)
    for (int idx = tid; idx < 8192; idx += 256) {
        int r = idx & 3, lane = (idx >> 2) & 31, ks = (idx >> 7) & 7, s = idx >> 10;
        int l4 = lane >> 2, q = lane & 3;
        int o  = s * 16 + l4 + (r & 1) * 8;
        int ci = ks * 16 + 2 * q + ((r >> 1) & 1) * 8;
        float v0 = (o < 64) ? g_w[o * 128 + ci]     : phi_w[(o - 64) * 128 + ci];
        float v1 = (o < 64) ? g_w[o * 128 + ci + 1] : phi_w[(o - 64) * 128 + ci + 1];
        d_A1f[idx] = pkbf(v0, v1);
    }
    // B frags GEMM3: b0:(k=2q|2q+1, n=Co) b1:(k+8); k=c, n=Co
    for (int idx = tid; idx < 4096; idx += 256) {
        int r = idx & 1, lane = (idx >> 1) & 31, nt = (idx >> 6) & 15, ks = idx >> 10;
        int l4 = lane >> 2, q = lane & 3;
        int Co = nt * 8 + l4;
        int c  = ks * 16 + 2 * q + r * 8;
        d_WwB[idx] = pkbf(W_w[Co * 64 + c], W_w[Co * 64 + c + 1]);
    }
}

// ---- smem layout (BYTE offsets) ----
// xT bf16 [z=128][136] stride 272B  (overlaid by f/y bf16 [z=128][72] stride 144B)
#define XT_B   0
#define F_B    0
#define GP_B   34816   // gp bf16 [c=64][72] stride 144B
#define AS_B   44032   // float a-partials [2][128]
#define BBW_B  45056   // float bb partials [2][64]
#define GB_B   45568   // float[64]
#define PB_B   45824
#define WP_B   46080
#define AL_B   46336   // float[128]
#define BE_B   46848
#define VT_B   47360
#define SMEM_BYTES 47872

__global__ void __launch_bounds__(THREADS, 2)
nonlocal_kernel(const float* __restrict__ x,
                const float* __restrict__ g_b,
                const float* __restrict__ phi_b,
                const float* __restrict__ cat_w,
                float* __restrict__ out)
{
    extern __shared__ char smc[];
    float* AS  = (float*)(smc + AS_B);
    float* BBW = (float*)(smc + BBW_B);
    float* GB  = (float*)(smc + GB_B);
    float* PB  = (float*)(smc + PB_B);
    float* WP  = (float*)(smc + WP_B);
    float* AL  = (float*)(smc + AL_B);
    float* BE  = (float*)(smc + BE_B);
    float* VT  = (float*)(smc + VT_B);

    const int tid  = threadIdx.x;
    const int lane = tid & 31;
    const int wid  = tid >> 5;     // 0..7
    const int q    = lane & 3;
    const int l4   = lane >> 2;

    const int n  = blockIdx.x;
    const int b  = n >> 10;
    const int wh = n & 1023;
    const size_t gbase = (size_t)b * 16777216 + (size_t)wh * 128;  // + Ci*131072 + z
    const float* xg = x + gbase;

    // ---- stage A: load x transposed -> bf16 xT[z][Ci] ----
    #pragma unroll
    for (int it = 0; it < 16; it++) {
        int g = wid * 16 + it;
        int c0 = 4 * (g >> 2), zoff = 32 * (g & 3);
        int z = zoff + lane;
        float v0 = xg[(size_t)(c0 + 0) * 131072 + z];
        float v1 = xg[(size_t)(c0 + 1) * 131072 + z];
        float v2 = xg[(size_t)(c0 + 2) * 131072 + z];
        float v3 = xg[(size_t)(c0 + 3) * 131072 + z];
        *(uint2*)(smc + XT_B + z * 272 + 2 * c0) = make_uint2(pkbf(v0, v1), pkbf(v2, v3));
    }
    if (tid < 128) { VT[tid] = d_vt[tid]; AL[tid] = d_alpha[tid]; BE[tid] = d_beta[tid]; }
    if (tid < 64)  { GB[tid] = g_b[tid]; PB[tid] = phi_b[tid]; WP[tid] = cat_w[64 + tid]; }
    __syncthreads();

    // ---- a[z] partials over all 256 threads (Ci halves) ----
    {
        const int z = tid & 127, h = tid >> 7;
        float s = h ? 0.f : d_ct;
        const uint4* p = (const uint4*)(smc + XT_B + z * 272 + h * 128);
        #pragma unroll
        for (int i = 0; i < 8; i++) {
            uint4 u = p[i];
            int c0 = h * 64 + 8 * i;
            s = fmaf(VT[c0 + 0], bf_lo(u.x), s); s = fmaf(VT[c0 + 1], bf_hi(u.x), s);
            s = fmaf(VT[c0 + 2], bf_lo(u.y), s); s = fmaf(VT[c0 + 3], bf_hi(u.y), s);
            s = fmaf(VT[c0 + 4], bf_lo(u.z), s); s = fmaf(VT[c0 + 5], bf_hi(u.z), s);
            s = fmaf(VT[c0 + 6], bf_lo(u.w), s); s = fmaf(VT[c0 + 7], bf_hi(u.w), s);
        }
        AS[h * 128 + z] = s;
    }

    // ---- GEMM1: warp grid 4 o-strips(32) x 2 z-halves(64); K=128, 8 ks ----
    const int oz = wid & 3;
    const int zh = wid >> 2;
    const int zb = zh * 64;

    float d1[2][8][4];
    #pragma unroll
    for (int mt = 0; mt < 2; mt++)
        #pragma unroll
        for (int nt = 0; nt < 8; nt++)
            #pragma unroll
            for (int r = 0; r < 4; r++) d1[mt][nt][r] = 0.f;

    {
        const uint4* gA0 = ((const uint4*)d_A1f) + (oz * 2) * 256;   // strip stride 8ks*32
        const uint4* gA1 = gA0 + 256;
        uint4 af0 = gA0[lane], af1 = gA1[lane];
        #pragma unroll 1
        for (int ks = 0; ks < 8; ks++) {
            uint4 c0 = af0, c1 = af1;
            if (ks < 7) { af0 = gA0[(ks + 1) * 32 + lane]; af1 = gA1[(ks + 1) * 32 + lane]; }
            const char* xrow = smc + XT_B + (zb + l4) * 272 + 32 * ks + 4 * q;
            #pragma unroll
            for (int nt = 0; nt < 8; nt++) {
                uint32_t b0 = *(const uint32_t*)(xrow + nt * 8 * 272);
                uint32_t b1 = *(const uint32_t*)(xrow + nt * 8 * 272 + 16);
                mma16(d1[0][nt], c0.x, c0.y, c0.z, c0.w, b0, b1);
                mma16(d1[1][nt], c1.x, c1.y, c1.z, c1.w, b0, b1);
            }
        }
    }
    __syncthreads();   // all xT reads done -> overlay (f) writable later

    // ---- epi1: pool z-pairs; g -> gp bf16 [c][j], phi -> bb partials ----
    if (oz < 2) {
        #pragma unroll
        for (int mt = 0; mt < 2; mt++) {
            const int o0 = oz * 32 + 16 * mt + l4, o1 = o0 + 8;
            const float gb0 = GB[o0], gb1 = GB[o1];
            #pragma unroll
            for (int nt = 0; nt < 8; nt++) {
                int j = zb / 2 + 4 * nt + q;
                float g0 = (fmaxf(d1[mt][nt][0], d1[mt][nt][1]) + gb0) * 0.015625f;
                float g1 = (fmaxf(d1[mt][nt][2], d1[mt][nt][3]) + gb1) * 0.015625f;
                *(__nv_bfloat16*)(smc + GP_B + o0 * 144 + 2 * j) = __float2bfloat16(g0);
                *(__nv_bfloat16*)(smc + GP_B + o1 * 144 + 2 * j) = __float2bfloat16(g1);
            }
        }
    } else {
        #pragma unroll
        for (int nt = 0; nt < 8; nt++) {
            float v = 0.f;
            #pragma unroll
            for (int mt = 0; mt < 2; mt++) {
                const int p0 = (oz - 2) * 32 + 16 * mt + l4, p1 = p0 + 8;
                v += WP[p0] * (fmaxf(d1[mt][nt][0], d1[mt][nt][1]) + PB[p0])
                   + WP[p1] * (fmaxf(d1[mt][nt][2], d1[mt][nt][3]) + PB[p1]);
            }
            v += __shfl_xor_sync(0xFFFFFFFFu, v, 16);
            v += __shfl_xor_sync(0xFFFFFFFFu, v, 8);
            v += __shfl_xor_sync(0xFFFFFFFFu, v, 4);
            if (l4 == 0) BBW[(oz - 2) * 64 + zb / 2 + 4 * nt + q] = v;
        }
    }
    __syncthreads();

    {   // f[z][j] = relu(a[z] + bb[j])  -> bf16 [z][144B]
        const int z = tid >> 1, half = tid & 1;
        const float az = AS[z] + AS[128 + z];
        #pragma unroll
        for (int jj = 0; jj < 8; jj++) {
            int j = half * 32 + 4 * jj;
            float f0 = fmaxf(az + BBW[j + 0] + BBW[64 + j + 0], 0.f);
            float f1 = fmaxf(az + BBW[j + 1] + BBW[64 + j + 1], 0.f);
            float f2 = fmaxf(az + BBW[j + 2] + BBW[64 + j + 2], 0.f);
            float f3 = fmaxf(az + BBW[j + 3] + BBW[64 + j + 3], 0.f);
            *(uint2*)(smc + F_B + z * 144 + 2 * j) = make_uint2(pkbf(f0, f1), pkbf(f2, f3));
        }
    }
    __syncthreads();

    // ---- GEMM2: D2[z][c] = f @ gp; warp = z-strip 16 (wid); K=64, 4 ks ----
    {
        float d2[8][4];
        #pragma unroll
        for (int nt = 0; nt < 8; nt++)
            #pragma unroll
            for (int r = 0; r < 4; r++) d2[nt][r] = 0.f;

        #pragma unroll 1
        for (int ks = 0; ks < 4; ks++) {
            const char* fr = smc + F_B + (16 * wid + l4) * 144 + 32 * ks + 4 * q;
            uint32_t a0 = *(const uint32_t*)(fr);
            uint32_t a1 = *(const uint32_t*)(fr + 8 * 144);
            uint32_t a2 = *(const uint32_t*)(fr + 16);
            uint32_t a3 = *(const uint32_t*)(fr + 8 * 144 + 16);
            const char* gr = smc + GP_B + l4 * 144 + 32 * ks + 4 * q;
            #pragma unroll
            for (int nt = 0; nt < 8; nt++) {
                uint32_t b0 = *(const uint32_t*)(gr + nt * 8 * 144);
                uint32_t b1 = *(const uint32_t*)(gr + nt * 8 * 144 + 16);
                mma16(d2[nt], a0, a1, a2, a3, b0, b1);
            }
        }
        // epi2: y (bf16) overwrites own f strip
        #pragma unroll
        for (int nt = 0; nt < 8; nt++) {
            int cbyte = 2 * (8 * nt + 2 * q);
            *(uint32_t*)(smc + F_B + (16 * wid + l4) * 144 + cbyte)       = pkbf(d2[nt][0], d2[nt][1]);
            *(uint32_t*)(smc + F_B + (16 * wid + l4 + 8) * 144 + cbyte)   = pkbf(d2[nt][2], d2[nt][3]);
        }
    }
    __syncthreads();   // y read cross-warp in GEMM3

    // ---- GEMM3: warp grid 4 z-strips(32) x 2 Co-halves(64); K=64, 4 ks ----
    {
        const int zq3 = wid >> 1, ch = wid & 1;
        const int zb3 = zq3 * 32, cob = ch * 64;

        float d3[2][8][4];
        #pragma unroll
        for (int mt = 0; mt < 2; mt++)
            #pragma unroll
            for (int nt = 0; nt < 8; nt++)
                #pragma unroll
                for (int r = 0; r < 4; r++) d3[mt][nt][r] = 0.f;

        const uint2* gB = (const uint2*)d_WwB;
        #pragma unroll 1
        for (int ks = 0; ks < 4; ks++) {
            const char* yr0 = smc + F_B + (zb3 + l4) * 144 + 32 * ks + 4 * q;
            const char* yr1 = yr0 + 16 * 144;
            uint32_t a00 = *(const uint32_t*)(yr0);
            uint32_t a01 = *(const uint32_t*)(yr0 + 8 * 144);
            uint32_t a02 = *(const uint32_t*)(yr0 + 16);
            uint32_t a03 = *(const uint32_t*)(yr0 + 8 * 144 + 16);
            uint32_t a10 = *(const uint32_t*)(yr1);
            uint32_t a11 = *(const uint32_t*)(yr1 + 8 * 144);
            uint32_t a12 = *(const uint32_t*)(yr1 + 16);
            uint32_t a13 = *(const uint32_t*)(yr1 + 8 * 144 + 16);
            #pragma unroll
            for (int nt = 0; nt < 8; nt++) {
                uint2 bw = gB[(ks * 16 + ch * 8 + nt) * 32 + lane];
                mma16(d3[0][nt], a00, a01, a02, a03, bw.x, bw.y);
                mma16(d3[1][nt], a10, a11, a12, a13, bw.x, bw.y);
            }
        }

        // ---- epi3: out = D3*alpha + beta + x (fp32, direct) ----
        #pragma unroll
        for (int mt = 0; mt < 2; mt++) {
            const int z0 = zb3 + 16 * mt + l4, z1 = z0 + 8;
            #pragma unroll
            for (int nt = 0; nt < 8; nt++) {
                int Co0 = cob + 8 * nt + 2 * q, Co1 = Co0 + 1;
                float al0 = AL[Co0], be0 = BE[Co0];
                float al1 = AL[Co1], be1 = BE[Co1];
                size_t p00 = gbase + (size_t)Co0 * 131072 + z0;
                size_t p10 = gbase + (size_t)Co1 * 131072 + z0;
                size_t p01 = gbase + (size_t)Co0 * 131072 + z1;
                size_t p11 = gbase + (size_t)Co1 * 131072 + z1;
                out[p00] = fmaf(d3[mt][nt][0], al0, be0) + __ldg(x + p00);
                out[p10] = fmaf(d3[mt][nt][1], al1, be1) + __ldg(x + p10);
                out[p01] = fmaf(d3[mt][nt][2], al0, be0) + __ldg(x + p01);
                out[p11] = fmaf(d3[mt][nt][3], al1, be1) + __ldg(x + p11);
            }
        }
    }
}

extern "C" void kernel_launch(void* const* d_in, const int* in_sizes, int n_in,
                              void* d_out, int out_size)
{
    const float* x       = (const float*)d_in[0];
    const float* g_w     = (const float*)d_in[1];
    const float* g_b     = (const float*)d_in[2];
    const float* theta_w = (const float*)d_in[3];
    const float* theta_b = (const float*)d_in[4];
    const float* phi_w   = (const float*)d_in[5];
    const float* phi_b   = (const float*)d_in[6];
    const float* cat_w   = (const float*)d_in[7];
    const float* W_w     = (const float*)d_in[8];
    const float* W_b     = (const float*)d_in[9];
    const float* bn_g    = (const float*)d_in[10];
    const float* bn_b    = (const float*)d_in[11];
    const float* bn_m    = (const float*)d_in[12];
    const float* bn_v    = (const float*)d_in[13];

    cudaFuncSetAttribute(nonlocal_kernel,
                         cudaFuncAttributeMaxDynamicSharedMemorySize, SMEM_BYTES);

    setup_kernel<<<1, 256>>>(theta_w, theta_b, cat_w, W_b,
                             bn_g, bn_b, bn_m, bn_v, g_w, phi_w, W_w);
    nonlocal_kernel<<<N_TILES, THREADS, SMEM_BYTES>>>(x, g_b, phi_b, cat_w,
                                                      (float*)d_out);
}

// round 15
// speedup vs baseline: 1.6174x; 1.0061x over previous
#include <cuda_runtime.h>
#include <cuda_bf16.h>
#include <cstdint>

// B=2, C=128, IC=64, W=H=32, Z=128, nz=64. 2048 tiles of x[C=128][Z=128].
// R14 = R12 (bf16 m16n8k16) + ldmatrix operand loads + a[z] folded into load.
//   GEMM1 D1[o=128][z=128] = Wgp[o][Ci] @ x[Ci][z]   (g rows 0..63, phi 64..127)
//   epi1: pool z-pairs in-register; g -> gp[c][j]/64 bf16, phi -> bb partials
//   GEMM2 D2[z][c=64] = f @ gp (f bf16), y in place (bf16)
//   GEMM3 D3[z][Co=128] = y @ Ww^T ; out = D3*alpha + beta + x (fp32 epi)

#define N_TILES 2048
#define THREADS 256

__device__ __forceinline__ uint32_t pkbf(float lo, float hi) {
    uint32_t r;
    asm("cvt.rn.bf16x2.f32 %0, %1, %2;" : "=r"(r) : "f"(hi), "f"(lo));
    return r;
}
__device__ __forceinline__ void mma16(float* d, uint32_t a0, uint32_t a1, uint32_t a2,
                                      uint32_t a3, uint32_t b0, uint32_t b1) {
    asm volatile("mma.sync.aligned.m16n8k16.row.col.f32.bf16.bf16.f32 "
                 "{%0,%1,%2,%3}, {%4,%5,%6,%7}, {%8,%9}, {%0,%1,%2,%3};"
                 : "+f"(d[0]), "+f"(d[1]), "+f"(d[2]), "+f"(d[3])
                 : "r"(a0), "r"(a1), "r"(a2), "r"(a3), "r"(b0), "r"(b1));
}
__device__ __forceinline__ void ldsm4(uint32_t& r0, uint32_t& r1, uint32_t& r2,
                                      uint32_t& r3, uint32_t addr) {
    asm volatile("ldmatrix.sync.aligned.m8n8.x4.shared.b16 {%0,%1,%2,%3}, [%4];"
                 : "=r"(r0), "=r"(r1), "=r"(r2), "=r"(r3) : "r"(addr));
}

// ---- precomputed globals ----
__device__ float d_vt[128];      // cat_w[:64]^T @ theta_w (theta conv collapsed)
__device__ float d_ct;
__device__ float d_alpha[128];
__device__ float d_beta[128];
__device__ __align__(16) uint32_t d_A1f[8192];  // Wgp bf16 frags [strip8][ks8][lane32][r4]
__device__ __align__(8)  uint32_t d_WwB[4096];  // Ww  bf16 frags [ks4][nt16][lane32][r2]

__global__ void setup_kernel(const float* __restrict__ theta_w,
                             const float* __restrict__ theta_b,
                             const float* __restrict__ cat_w,
                             const float* __restrict__ W_b,
                             const float* __restrict__ bn_g,
                             const float* __restrict__ bn_b,
                             const float* __restrict__ bn_m,
                             const float* __restrict__ bn_v,
                             const float* __restrict__ g_w,
                             const float* __restrict__ phi_w,
                             const float* __restrict__ W_w)
{
    int tid = threadIdx.x;  // 256
    if (tid < 128) {
        float s = 0.f;
        for (int ic = 0; ic < 64; ic++) s += cat_w[ic] * theta_w[ic * 128 + tid];
        d_vt[tid] = s;
        float a = bn_g[tid] * rsqrtf(bn_v[tid] + 1e-5f);
        d_alpha[tid] = a;
        d_beta[tid]  = (W_b[tid] - bn_m[tid]) * a + bn_b[tid];
    }
    if (tid == 0) {
        float s = 0.f;
        for (int ic = 0; ic < 64; ic++) s += cat_w[ic] * theta_b[ic];
        d_ct = s;
    }
    // A frags GEMM1 (m16n8k16): a0:(row,2q..) a1:(row+8) a2:(row,2q+8) a3:(row+8,2q+8)
    for (int idx = tid; idx < 8192; idx += 256) {
        int r = idx & 3, lane = (idx >> 2) & 31, ks = (idx >> 7) & 7, s = idx >> 10;
        int l4 = lane >> 2, q = lane & 3;
        int o  = s * 16 + l4 + (r & 1) * 8;
        int ci = ks * 16 + 2 * q + ((r >> 1) & 1) * 8;
        float v0 = (o < 64) ? g_w[o * 128 + ci]     : phi_w[(o - 64) * 128 + ci];
        float v1 = (o < 64) ? g_w[o * 128 + ci + 1] : phi_w[(o - 64) * 128 + ci + 1];
        d_A1f[idx] = pkbf(v0, v1);
    }
    // B frags GEMM3: b0:(k=2q, n=Co) b1:(k+8)
    for (int idx = tid; idx < 4096; idx += 256) {
        int r = idx & 1, lane = (idx >> 1) & 31, nt = (idx >> 6) & 15, ks = idx >> 10;
        int l4 = lane >> 2, q = lane & 3;
        int Co = nt * 8 + l4;
        int c  = ks * 16 + 2 * q + r * 8;
        d_WwB[idx] = pkbf(W_w[Co * 64 + c], W_w[Co * 64 + c + 1]);
    }
}

// ---- smem layout (BYTE offsets) ----
#define XT_B   0       // xT bf16 [z=128][272B]  (overlaid by f/y bf16 [z=128][144B])
#define F_B    0
#define GP_B   34816   // gp bf16 [c=64][144B]
#define AS_B   44032   // a partials fp32 [8][128]
#define BBW_B  48128   // bb partials fp32 [2][64]
#define GB_B   48640
#define PB_B   48896
#define WP_B   49152
#define AL_B   49408
#define BE_B   49920
#define SMEM_BYTES 50432

__global__ void __launch_bounds__(THREADS, 2)
nonlocal_kernel(const float* __restrict__ x,
                const float* __restrict__ g_b,
                const float* __restrict__ phi_b,
                const float* __restrict__ cat_w,
                float* __restrict__ out)
{
    extern __shared__ char smc[];
    float* AS  = (float*)(smc + AS_B);
    float* BBW = (float*)(smc + BBW_B);
    float* GB  = (float*)(smc + GB_B);
    float* PB  = (float*)(smc + PB_B);
    float* WP  = (float*)(smc + WP_B);
    float* AL  = (float*)(smc + AL_B);
    float* BE  = (float*)(smc + BE_B);

    const int tid  = threadIdx.x;
    const int lane = tid & 31;
    const int wid  = tid >> 5;     // 0..7
    const int q    = lane & 3;
    const int l4   = lane >> 2;
    const int brow = lane & 7;
    const int bs1  = (lane >> 3) & 1;   // sel bit 0
    const int bs2  = (lane >> 4) & 1;   // sel bit 1

    const int n  = blockIdx.x;
    const int b  = n >> 10;
    const int wh = n & 1023;
    const size_t gbase = (size_t)b * 16777216 + (size_t)wh * 128;  // + Ci*131072 + z
    const float* xg = x + gbase;

    // ---- stage A: load x transposed -> bf16 xT[z][Ci]; fold a[z] partials ----
    {
        float4 vt4[4];
        #pragma unroll
        for (int k = 0; k < 4; k++) vt4[k] = ((const float4*)d_vt)[wid * 4 + k];
        float ap[4] = {0.f, 0.f, 0.f, 0.f};
        #pragma unroll
        for (int it = 0; it < 16; it++) {
            int g = wid * 16 + it;
            int c0 = 4 * (g >> 2), zsel = g & 3;
            int z = 32 * zsel + lane;
            float v0 = xg[(size_t)(c0 + 0) * 131072 + z];
            float v1 = xg[(size_t)(c0 + 1) * 131072 + z];
            float v2 = xg[(size_t)(c0 + 2) * 131072 + z];
            float v3 = xg[(size_t)(c0 + 3) * 131072 + z];
            *(uint2*)(smc + XT_B + z * 272 + 2 * c0) = make_uint2(pkbf(v0, v1), pkbf(v2, v3));
            float4 w = vt4[it >> 2];
            ap[zsel] = fmaf(w.x, v0, fmaf(w.y, v1, fmaf(w.z, v2, fmaf(w.w, v3, ap[zsel]))));
        }
        #pragma unroll
        for (int zsel = 0; zsel < 4; zsel++)
            AS[wid * 128 + 32 * zsel + lane] = ap[zsel];
    }
    if (tid < 128) { AL[tid] = d_alpha[tid]; BE[tid] = d_beta[tid]; }
    if (tid < 64)  { GB[tid] = g_b[tid]; PB[tid] = phi_b[tid]; WP[tid] = cat_w[64 + tid]; }
    __syncthreads();

    // ---- GEMM1: warp grid 4 o-strips(32) x 2 z-halves(64); K=128, 8 ks ----
    const int oz = wid & 3;
    const int zh = wid >> 2;
    const int zb = zh * 64;

    float d1[2][8][4];
    #pragma unroll
    for (int mt = 0; mt < 2; mt++)
        #pragma unroll
        for (int nt = 0; nt < 8; nt++)
            #pragma unroll
            for (int r = 0; r < 4; r++) d1[mt][nt][r] = 0.f;

    {
        const uint4* gA0 = ((const uint4*)d_A1f) + (oz * 2) * 256;
        const uint4* gA1 = gA0 + 256;
        // B ldmatrix base: m0(rows nt,col0) m1(rows nt,col16) m2(rows nt+8,col0) m3(+16)
        uint32_t xb = (uint32_t)__cvta_generic_to_shared(smc + XT_B)
                    + (uint32_t)((zb + bs2 * 8 + brow) * 272 + bs1 * 16);
        uint4 af0 = gA0[lane], af1 = gA1[lane];
        #pragma unroll 1
        for (int ks = 0; ks < 8; ks++) {
            uint4 c0 = af0, c1 = af1;
            if (ks < 7) { af0 = gA0[(ks + 1) * 32 + lane]; af1 = gA1[(ks + 1) * 32 + lane]; }
            #pragma unroll
            for (int ntp = 0; ntp < 4; ntp++) {
                uint32_t b0, b1, b2, b3;
                ldsm4(b0, b1, b2, b3, xb + (uint32_t)(ntp * 16 * 272 + 32 * ks));
                mma16(d1[0][2 * ntp],     c0.x, c0.y, c0.z, c0.w, b0, b1);
                mma16(d1[0][2 * ntp + 1], c0.x, c0.y, c0.z, c0.w, b2, b3);
                mma16(d1[1][2 * ntp],     c1.x, c1.y, c1.z, c1.w, b0, b1);
                mma16(d1[1][2 * ntp + 1], c1.x, c1.y, c1.z, c1.w, b2, b3);
            }
        }
    }
    __syncthreads();   // xT reads done -> overlay writable

    // ---- epi1: pool z-pairs; g -> gp bf16 [c][j], phi -> bb partials ----
    if (oz < 2) {
        #pragma unroll
        for (int mt = 0; mt < 2; mt++) {
            const int o0 = oz * 32 + 16 * mt + l4, o1 = o0 + 8;
            const float gb0 = GB[o0], gb1 = GB[o1];
            #pragma unroll
            for (int nt = 0; nt < 8; nt++) {
                int j = zb / 2 + 4 * nt + q;
                float g0 = (fmaxf(d1[mt][nt][0], d1[mt][nt][1]) + gb0) * 0.015625f;
                float g1 = (fmaxf(d1[mt][nt][2], d1[mt][nt][3]) + gb1) * 0.015625f;
                *(__nv_bfloat16*)(smc + GP_B + o0 * 144 + 2 * j) = __float2bfloat16(g0);
                *(__nv_bfloat16*)(smc + GP_B + o1 * 144 + 2 * j) = __float2bfloat16(g1);
            }
        }
    } else {
        #pragma unroll
        for (int nt = 0; nt < 8; nt++) {
            float v = 0.f;
            #pragma unroll
            for (int mt = 0; mt < 2; mt++) {
                const int p0 = (oz - 2) * 32 + 16 * mt + l4, p1 = p0 + 8;
                v += WP[p0] * (fmaxf(d1[mt][nt][0], d1[mt][nt][1]) + PB[p0])
                   + WP[p1] * (fmaxf(d1[mt][nt][2], d1[mt][nt][3]) + PB[p1]);
            }
            v += __shfl_xor_sync(0xFFFFFFFFu, v, 16);
            v += __shfl_xor_sync(0xFFFFFFFFu, v, 8);
            v += __shfl_xor_sync(0xFFFFFFFFu, v, 4);
            if (l4 == 0) BBW[(oz - 2) * 64 + zb / 2 + 4 * nt + q] = v;
        }
    }
    __syncthreads();

    {   // f[z][j] = relu(a[z] + bb[j]) -> bf16; a = ct + 8 group partials
        const int z = tid >> 1, half = tid & 1;
        float az = d_ct;
        #pragma unroll
        for (int g = 0; g < 8; g++) az += AS[g * 128 + z];
        #pragma unroll
        for (int jj = 0; jj < 8; jj++) {
            int j = half * 32 + 4 * jj;
            float f0 = fmaxf(az + BBW[j + 0] + BBW[64 + j + 0], 0.f);
            float f1 = fmaxf(az + BBW[j + 1] + BBW[64 + j + 1], 0.f);
            float f2 = fmaxf(az + BBW[j + 2] + BBW[64 + j + 2], 0.f);
            float f3 = fmaxf(az + BBW[j + 3] + BBW[64 + j + 3], 0.f);
            *(uint2*)(smc + F_B + z * 144 + 2 * j) = make_uint2(pkbf(f0, f1), pkbf(f2, f3));
        }
    }
    __syncthreads();

    // ---- GEMM2: D2[z][c] = f @ gp; warp = z-strip 16 (wid); K=64, 4 ks ----
    {
        float d2[8][4];
        #pragma unroll
        for (int nt = 0; nt < 8; nt++)
            #pragma unroll
            for (int r = 0; r < 4; r++) d2[nt][r] = 0.f;

        // A base: m0(rows0-7,c0) m1(rows8-15,c0) m2(rows0-7,c16) m3(rows8-15,c16)
        uint32_t fa = (uint32_t)__cvta_generic_to_shared(smc + F_B)
                    + (uint32_t)((16 * wid + bs1 * 8 + brow) * 144 + bs2 * 16);
        uint32_t gb_ = (uint32_t)__cvta_generic_to_shared(smc + GP_B)
                    + (uint32_t)((bs2 * 8 + brow) * 144 + bs1 * 16);
        #pragma unroll 1
        for (int ks = 0; ks < 4; ks++) {
            uint32_t a0, a1, a2, a3;
            ldsm4(a0, a1, a2, a3, fa + (uint32_t)(32 * ks));
            #pragma unroll
            for (int ntp = 0; ntp < 4; ntp++) {
                uint32_t b0, b1, b2, b3;
                ldsm4(b0, b1, b2, b3, gb_ + (uint32_t)(ntp * 16 * 144 + 32 * ks));
                mma16(d2[2 * ntp],     a0, a1, a2, a3, b0, b1);
                mma16(d2[2 * ntp + 1], a0, a1, a2, a3, b2, b3);
            }
        }
        __syncthreads();   // gp reads done; f strip rewrite below is warp-local
        // epi2: y (bf16) overwrites own f strip
        #pragma unroll
        for (int nt = 0; nt < 8; nt++) {
            int cbyte = 2 * (8 * nt + 2 * q);
            *(uint32_t*)(smc + F_B + (16 * wid + l4) * 144 + cbyte)     = pkbf(d2[nt][0], d2[nt][1]);
            *(uint32_t*)(smc + F_B + (16 * wid + l4 + 8) * 144 + cbyte) = pkbf(d2[nt][2], d2[nt][3]);
        }
    }
    __syncthreads();   // y read cross-warp in GEMM3

    // ---- GEMM3: warp grid 4 z-strips(32) x 2 Co-halves(64); K=64, 4 ks ----
    {
        const int zq3 = wid >> 1, ch = wid & 1;
        const int zb3 = zq3 * 32, cob = ch * 64;

        float d3[2][8][4];
        #pragma unroll
        for (int mt = 0; mt < 2; mt++)
            #pragma unroll
            for (int nt = 0; nt < 8; nt++)
                #pragma unroll
                for (int r = 0; r < 4; r++) d3[mt][nt][r] = 0.f;

        uint32_t ya0 = (uint32_t)__cvta_generic_to_shared(smc + F_B)
                     + (uint32_t)((zb3 + bs1 * 8 + brow) * 144 + bs2 * 16);
        const uint2* gB = (const uint2*)d_WwB;
        #pragma unroll 1
        for (int ks = 0; ks < 4; ks++) {
            uint32_t a00, a01, a02, a03, a10, a11, a12, a13;
            ldsm4(a00, a01, a02, a03, ya0 + (uint32_t)(32 * ks));
            ldsm4(a10, a11, a12, a13, ya0 + (uint32_t)(16 * 144 + 32 * ks));
            #pragma unroll
            for (int nt = 0; nt < 8; nt++) {
                uint2 bw = gB[(ks * 16 + ch * 8 + nt) * 32 + lane];
                mma16(d3[0][nt], a00, a01, a02, a03, bw.x, bw.y);
                mma16(d3[1][nt], a10, a11, a12, a13, bw.x, bw.y);
            }
        }

        // ---- epi3: out = D3*alpha + beta + x (fp32, direct) ----
        #pragma unroll
        for (int mt = 0; mt < 2; mt++) {
            const int z0 = zb3 + 16 * mt + l4, z1 = z0 + 8;
            #pragma unroll
            for (int nt = 0; nt < 8; nt++) {
                int Co0 = cob + 8 * nt + 2 * q, Co1 = Co0 + 1;
                float al0 = AL[Co0], be0 = BE[Co0];
                float al1 = AL[Co1], be1 = BE[Co1];
                size_t p00 = gbase + (size_t)Co0 * 131072 + z0;
                size_t p10 = gbase + (size_t)Co1 * 131072 + z0;
                size_t p01 = gbase + (size_t)Co0 * 131072 + z1;
                size_t p11 = gbase + (size_t)Co1 * 131072 + z1;
                out[p00] = fmaf(d3[mt][nt][0], al0, be0) + __ldg(x + p00);
                out[p10] = fmaf(d3[mt][nt][1], al1, be1) + __ldg(x + p10);
                out[p01] = fmaf(d3[mt][nt][2], al0, be0) + __ldg(x + p01);
                out[p11] = fmaf(d3[mt][nt][3], al1, be1) + __ldg(x + p11);
            }
        }
    }
}

extern "C" void kernel_launch(void* const* d_in, const int* in_sizes, int n_in,
                              void* d_out, int out_size)
{
    const float* x       = (const float*)d_in[0];
    const float* g_w     = (const float*)d_in[1];
    const float* g_b     = (const float*)d_in[2];
    const float* theta_w = (const float*)d_in[3];
    const float* theta_b = (const float*)d_in[4];
    const float* phi_w   = (const float*)d_in[5];
    const float* phi_b   = (const float*)d_in[6];
    const float* cat_w   = (const float*)d_in[7];
    const float* W_w     = (const float*)d_in[8];
    const float* W_b     = (const float*)d_in[9];
    const float* bn_g    = (const float*)d_in[10];
    const float* bn_b    = (const float*)d_in[11];
    const float* bn_m    = (const float*)d_in[12];
    const float* bn_v    = (const float*)d_in[13];

    cudaFuncSetAttribute(nonlocal_kernel,
                         cudaFuncAttributeMaxDynamicSharedMemorySize, SMEM_BYTES);

    setup_kernel<<<1, 256>>>(theta_w, theta_b, cat_w, W_b,
                             bn_g, bn_b, bn_m, bn_v, g_w, phi_w, W_w);
    nonlocal_kernel<<<N_TILES, THREADS, SMEM_BYTES>>>(x, g_b, phi_b, cat_w,
                                                      (float*)d_out);
}